// round 3
// baseline (speedup 1.0000x reference)
#include <cuda_runtime.h>
#include <cuda_bf16.h>
#include <cstdint>

// Problem constants
#define Bn 64
#define Sn 512
#define Dn 256
#define Hn 256
#define Ln 9

// ---------------------------------------------------------------------------
// Static device scratch (allocation-free rule: __device__ globals)
// ---------------------------------------------------------------------------
// Xperm[dir][s][blk][b][jl]: input projection + bias, permuted so that block
// `blk` of the recurrence kernel reads a contiguous 1024-float tile per step.
// jl = m*4 + r maps to global gate row gj = m*256 + blk*4 + r.
__device__ float g_Xperm[2u * 512u * 64u * 1024u];      // 268 MB
__device__ float g_Hbuf[2u * 512u * 64u * 256u];        // 67 MB  (hf / hb all steps)
__device__ float g_hstate[2][2][Bn * Hn];               // [parity][dir]
__device__ float g_em[(size_t)Bn * Sn * Ln];            // emissions [b][s][l]
__device__ float g_res[Bn];
__device__ volatile unsigned g_barcnt[2];
__device__ volatile unsigned g_bargen[2];

// ---------------------------------------------------------------------------
// Fast pointwise
// ---------------------------------------------------------------------------
__device__ __forceinline__ float fsig(float x) { return 1.0f / (1.0f + __expf(-x)); }
__device__ __forceinline__ float ftanh(float x) { return 2.0f / (1.0f + __expf(-2.0f * x)) - 1.0f; }

// ---------------------------------------------------------------------------
// Kernel 1: embedding gather + input projection GEMM (+bias), permuted write.
// C[m][n] = sum_k E[x_m][k] * Wih[n][k] + bias[n],  m = s*64 + b.
// Tile 64x64, K-chunk 16, 256 threads, 4x4 register micro-tile.
// grid = (16 n-tiles, 512 s, 2 dirs)
// ---------------------------------------------------------------------------
__global__ void embed_inproj_kernel(const int* __restrict__ x,
                                    const float* __restrict__ E,
                                    const float* __restrict__ Wih_f,
                                    const float* __restrict__ b_f,
                                    const float* __restrict__ Wih_b,
                                    const float* __restrict__ b_b) {
    const int dir = blockIdx.z;
    const float* __restrict__ W = dir ? Wih_b : Wih_f;
    const float* __restrict__ bias = dir ? b_b : b_f;
    const int s = blockIdx.y;
    const int n0 = blockIdx.x * 64;

    __shared__ float sA[16][68];
    __shared__ float sB[16][68];
    __shared__ int srow[64];

    const int tid = threadIdx.x;
    if (tid < 64) srow[tid] = x[tid * Sn + s];   // x[b][s], b = row
    __syncthreads();

    const int tm = tid & 15;          // 4 rows
    const int tn = tid >> 4;          // 4 cols
    const int lrow = tid >> 2;        // loader row 0..63
    const int kq = tid & 3;           // loader k-quad

    float acc[4][4];
#pragma unroll
    for (int c = 0; c < 4; c++)
#pragma unroll
        for (int d = 0; d < 4; d++) acc[c][d] = 0.0f;

    for (int k0 = 0; k0 < 256; k0 += 16) {
        float4 a4 = *reinterpret_cast<const float4*>(&E[(size_t)srow[lrow] * Dn + k0 + kq * 4]);
        float4 b4 = *reinterpret_cast<const float4*>(&W[(size_t)(n0 + lrow) * Dn + k0 + kq * 4]);
        __syncthreads();   // previous compute done reading smem
        sA[kq * 4 + 0][lrow] = a4.x; sA[kq * 4 + 1][lrow] = a4.y;
        sA[kq * 4 + 2][lrow] = a4.z; sA[kq * 4 + 3][lrow] = a4.w;
        sB[kq * 4 + 0][lrow] = b4.x; sB[kq * 4 + 1][lrow] = b4.y;
        sB[kq * 4 + 2][lrow] = b4.z; sB[kq * 4 + 3][lrow] = b4.w;
        __syncthreads();
#pragma unroll
        for (int kk = 0; kk < 16; kk++) {
            float4 ra = *reinterpret_cast<float4*>(&sA[kk][4 * tm]);
            float4 rb = *reinterpret_cast<float4*>(&sB[kk][4 * tn]);
            acc[0][0] += ra.x * rb.x; acc[0][1] += ra.x * rb.y; acc[0][2] += ra.x * rb.z; acc[0][3] += ra.x * rb.w;
            acc[1][0] += ra.y * rb.x; acc[1][1] += ra.y * rb.y; acc[1][2] += ra.y * rb.z; acc[1][3] += ra.y * rb.w;
            acc[2][0] += ra.z * rb.x; acc[2][1] += ra.z * rb.y; acc[2][2] += ra.z * rb.z; acc[2][3] += ra.z * rb.w;
            acc[3][0] += ra.w * rb.x; acc[3][1] += ra.w * rb.y; acc[3][2] += ra.w * rb.z; acc[3][3] += ra.w * rb.w;
        }
    }

    // Epilogue: add bias, permuted write.
    const int n = n0 + 4 * tn;              // 4-aligned gate row base
    const int blk = (n & 255) >> 2;
    const int mg = n >> 8;
    const size_t tile_base = (((size_t)dir * Sn + s) * 64 + blk) * 1024;
    float bx = bias[n + 0], by = bias[n + 1], bz = bias[n + 2], bw = bias[n + 3];
#pragma unroll
    for (int c = 0; c < 4; c++) {
        const int b = 4 * tm + c;
        float4 v;
        v.x = acc[c][0] + bx; v.y = acc[c][1] + by;
        v.z = acc[c][2] + bz; v.w = acc[c][3] + bw;
        *reinterpret_cast<float4*>(&g_Xperm[tile_base + (size_t)b * 16 + mg * 4]) = v;
    }
}

// ---------------------------------------------------------------------------
// Grid barrier among the 64 blocks of one direction (sense-reversing).
// ---------------------------------------------------------------------------
__device__ __forceinline__ void dir_barrier(int dir) {
    __threadfence();                 // publish this thread's global writes
    __syncthreads();
    if (threadIdx.x == 0) {
        unsigned g = g_bargen[dir];
        unsigned prev = atomicAdd((unsigned*)&g_barcnt[dir], 1u);
        if (prev == 63u) {
            g_barcnt[dir] = 0u;
            __threadfence();
            g_bargen[dir] = g + 1u;
        } else {
            while (g_bargen[dir] == g) { __nanosleep(64); }
        }
    }
    __syncthreads();
}

// ---------------------------------------------------------------------------
// Kernel 2: persistent bidirectional LSTM recurrence.
// 128 blocks (64 per dir), 256 threads. Block (dir, blk) owns gate rows
// {m*256 + blk*4 + r : m,r in 0..3} for all 64 batches; local jl = m*4+r.
// Per step: gates = Xtile + h_prev @ Whh_tile^T ; c/h update block-local;
// one grid barrier per step; h double-buffered in global.
// Inner loop vectorized: float4 along k; sh padded to 68 so LDS.128 across
// lanes (bank = (4*tb + c) mod 32) is conflict-free; sW reads are warp-
// uniform broadcasts.
// ---------------------------------------------------------------------------
__global__ void lstm_recur_kernel(const float* __restrict__ Whh_f,
                                  const float* __restrict__ Whh_b) {
    const int dir = blockIdx.x >> 6;
    const int blk = blockIdx.x & 63;
    const float* __restrict__ Whh = dir ? Whh_b : Whh_f;

    __shared__ float sW[16][256];   // stationary weight tile (16 gate rows)
    __shared__ float sh[64][68];    // h chunk [b][k2], padded for LDS.128
    __shared__ float sG[64][17];    // gates [b][jl]
    __shared__ float sC[64][4];     // cell state, persistent across steps

    const int tid = threadIdx.x;

    // Load stationary Whh tile: sW[jl][k] = Whh[(jl>>2)*256 + blk*4 + (jl&3)][k]
    for (int i = tid; i < 4096; i += 256) {
        int jl = i >> 8, k = i & 255;
        sW[jl][k] = Whh[(size_t)(((jl >> 2) << 8) + (blk << 2) + (jl & 3)) * Hn + k];
    }
    // Zero cell state and the parity-0 h buffer slice (this block owns b=blk row)
    {
        int ub = tid >> 2, ur = tid & 3;
        sC[ub][ur] = 0.0f;
        g_hstate[0][dir][blk * 256 + tid] = 0.0f;
    }
    dir_barrier(dir);

    const int tb = tid & 31;    // compute: b in {tb, tb+32}
    const int tj = tid >> 5;    // compute: jl in {tj, tj+8}
    const int ub = tid >> 2;    // update: batch
    const int ur = tid & 3;     // update: hidden col within block (r)

    for (int step = 0; step < 512; step++) {
        const int s = dir ? (511 - step) : step;
        const int par = step & 1;
        const float* __restrict__ hin = g_hstate[par][dir];
        float* __restrict__ hout = g_hstate[par ^ 1][dir];

        // Load X tile (1024 floats) into sG as the gate accumulator base.
        {
            const float* Xt = &g_Xperm[(((size_t)dir * Sn + s) * 64 + blk) * 1024];
            float4 v = *reinterpret_cast<const float4*>(&Xt[tid * 4]);
            int b = tid >> 2, jl = (tid & 3) * 4;
            sG[b][jl] = v.x; sG[b][jl + 1] = v.y; sG[b][jl + 2] = v.z; sG[b][jl + 3] = v.w;
        }

        float a00 = 0.f, a01 = 0.f, a10 = 0.f, a11 = 0.f;
#pragma unroll
        for (int kc = 0; kc < 4; kc++) {
            __syncthreads();   // prev chunk compute done; also orders sG X-writes
            // Load h chunk: sh[b][k2] = hin[b*256 + kc*64 + k2]  (L2, bypass L1)
            const int kb = kc << 6;
            for (int i = tid; i < 1024; i += 256) {
                int b = i >> 4;
                int k2 = (i & 15) * 4;
                float4 v = __ldcg(reinterpret_cast<const float4*>(&hin[b * 256 + kb + k2]));
                *reinterpret_cast<float4*>(&sh[b][k2]) = v;
            }
            __syncthreads();
#pragma unroll
            for (int kk = 0; kk < 16; kk++) {
                float4 h0 = *reinterpret_cast<const float4*>(&sh[tb][kk * 4]);
                float4 h1 = *reinterpret_cast<const float4*>(&sh[tb + 32][kk * 4]);
                float4 w0 = *reinterpret_cast<const float4*>(&sW[tj][kb + kk * 4]);
                float4 w1 = *reinterpret_cast<const float4*>(&sW[tj + 8][kb + kk * 4]);
                a00 += h0.x * w0.x + h0.y * w0.y + h0.z * w0.z + h0.w * w0.w;
                a01 += h0.x * w1.x + h0.y * w1.y + h0.z * w1.z + h0.w * w1.w;
                a10 += h1.x * w0.x + h1.y * w0.y + h1.z * w0.z + h1.w * w0.w;
                a11 += h1.x * w1.x + h1.y * w1.y + h1.z * w1.z + h1.w * w1.w;
            }
        }
        sG[tb][tj] += a00;      sG[tb][tj + 8] += a01;
        sG[tb + 32][tj] += a10; sG[tb + 32][tj + 8] += a11;
        __syncthreads();

        // Pointwise LSTM cell update (block-local: this block's 4 hidden cols)
        {
            float gi = sG[ub][0 + ur];
            float gf = sG[ub][4 + ur];
            float gg = sG[ub][8 + ur];
            float go = sG[ub][12 + ur];
            float c = sC[ub][ur];
            c = fsig(gf) * c + fsig(gi) * ftanh(gg);
            float h = fsig(go) * ftanh(c);
            sC[ub][ur] = c;
            const int hcol = (blk << 2) + ur;
            hout[ub * 256 + hcol] = h;
            g_Hbuf[(((size_t)dir * Sn + s) * Bn + ub) * Hn + hcol] = h;
        }
        dir_barrier(dir);
    }
}

// ---------------------------------------------------------------------------
// Kernel 3: emissions em[b][s][l] = [hf,hb] @ Wo + bo. One warp per (s,b).
// ---------------------------------------------------------------------------
__global__ void emissions_kernel(const float* __restrict__ Wo,
                                 const float* __restrict__ bo) {
    const int warp = (blockIdx.x * blockDim.x + threadIdx.x) >> 5;
    const int lane = threadIdx.x & 31;
    if (warp >= Bn * Sn) return;
    const int s = warp >> 6;
    const int b = warp & 63;
    const float* __restrict__ hf = &g_Hbuf[(((size_t)0 * Sn + s) * Bn + b) * Hn];
    const float* __restrict__ hb = &g_Hbuf[(((size_t)1 * Sn + s) * Bn + b) * Hn];

    float acc[9];
#pragma unroll
    for (int j = 0; j < 9; j++) acc[j] = 0.0f;

    for (int k = lane; k < 256; k += 32) {
        float vf = hf[k];
        float vb = hb[k];
        const float* w1 = &Wo[(size_t)k * Ln];
        const float* w2 = &Wo[(size_t)(256 + k) * Ln];
#pragma unroll
        for (int j = 0; j < 9; j++) acc[j] += vf * w1[j] + vb * w2[j];
    }
#pragma unroll
    for (int j = 0; j < 9; j++) {
        float v = acc[j];
#pragma unroll
        for (int o = 16; o; o >>= 1) v += __shfl_down_sync(0xffffffffu, v, o);
        if (lane == 0) g_em[((size_t)b * Sn + s) * Ln + j] = v + bo[j];
    }
}

// ---------------------------------------------------------------------------
// Kernel 4: CRF forward (logZ) + gold score, one block (1 warp) per batch.
// ---------------------------------------------------------------------------
__global__ void crf_kernel(const int* __restrict__ x,
                           const int* __restrict__ y,
                           const float* __restrict__ T,
                           const float* __restrict__ start,
                           const float* __restrict__ end) {
    const int b = blockIdx.x;
    const int lane = threadIdx.x;
    __shared__ float alpha[9];
    const float* __restrict__ em = &g_em[(size_t)b * Sn * Ln];

    float Tcol[9];
    if (lane < 9) {
#pragma unroll
        for (int i = 0; i < 9; i++) Tcol[i] = T[i * 9 + lane];
        alpha[lane] = start[lane] + em[lane];
    }
    __syncwarp();

    for (int t = 1; t < Sn; t++) {
        if (x[b * Sn + t] != 0) {
            float nv = 0.0f;
            if (lane < 9) {
                float mx = -3.4e38f;
                float v[9];
#pragma unroll
                for (int i = 0; i < 9; i++) {
                    v[i] = alpha[i] + Tcol[i];
                    mx = fmaxf(mx, v[i]);
                }
                float ssum = 0.0f;
#pragma unroll
                for (int i = 0; i < 9; i++) ssum += __expf(v[i] - mx);
                nv = mx + __logf(ssum) + em[t * Ln + lane];
            }
            __syncwarp();
            if (lane < 9) alpha[lane] = nv;
            __syncwarp();
        }
    }

    // logZ = logsumexp(alpha + end)
    float v = (lane < 9) ? (alpha[lane] + end[lane]) : -3.4e38f;
    float mx = v;
#pragma unroll
    for (int o = 16; o; o >>= 1) mx = fmaxf(mx, __shfl_xor_sync(0xffffffffu, mx, o));
    float e = (lane < 9) ? __expf(v - mx) : 0.0f;
#pragma unroll
    for (int o = 16; o; o >>= 1) e += __shfl_xor_sync(0xffffffffu, e, o);
    float logZ = mx + __logf(e);

    if (lane == 0) {
        const int y0 = y[b * Sn];
        float score = start[y0] + em[y0];
        int prev = y0;
        int msum = (x[b * Sn] != 0) ? 1 : 0;
        for (int t = 1; t < Sn; t++) {
            int yt = y[b * Sn + t];
            if (x[b * Sn + t] != 0) {
                score += T[prev * 9 + yt] + em[t * Ln + yt];
                msum++;
            }
            prev = yt;
        }
        int last = msum - 1;
        if (last < 0) last = 0;
        score += end[y[b * Sn + last]];
        g_res[b] = logZ - score;
    }
}

// ---------------------------------------------------------------------------
// Kernel 5: mean over batch -> scalar output
// ---------------------------------------------------------------------------
__global__ void reduce_kernel(float* __restrict__ out) {
    __shared__ float s[64];
    s[threadIdx.x] = g_res[threadIdx.x];
    __syncthreads();
    if (threadIdx.x == 0) {
        float t = 0.0f;
        for (int i = 0; i < 64; i++) t += s[i];
        out[0] = t * (1.0f / 64.0f);
    }
}

// ---------------------------------------------------------------------------
// Launch. Input order (metadata): x, y, E, Wih_f, Whh_f, b_f, Wih_b, Whh_b,
// b_b, Wo, bo, T, start, end. Output: scalar float.
// ---------------------------------------------------------------------------
extern "C" void kernel_launch(void* const* d_in, const int* in_sizes, int n_in,
                              void* d_out, int out_size) {
    const int*   x      = (const int*)  d_in[0];
    const int*   y      = (const int*)  d_in[1];
    const float* E      = (const float*)d_in[2];
    const float* Wih_f  = (const float*)d_in[3];
    const float* Whh_f  = (const float*)d_in[4];
    const float* b_f    = (const float*)d_in[5];
    const float* Wih_b  = (const float*)d_in[6];
    const float* Whh_b  = (const float*)d_in[7];
    const float* b_b    = (const float*)d_in[8];
    const float* Wo     = (const float*)d_in[9];
    const float* bo     = (const float*)d_in[10];
    const float* T      = (const float*)d_in[11];
    const float* start  = (const float*)d_in[12];
    const float* end    = (const float*)d_in[13];
    float* out = (float*)d_out;

    dim3 gemm_grid(16, 512, 2);
    embed_inproj_kernel<<<gemm_grid, 256>>>(x, E, Wih_f, b_f, Wih_b, b_b);
    lstm_recur_kernel<<<128, 256>>>(Whh_f, Whh_b);
    emissions_kernel<<<4096, 256>>>(Wo, bo);
    crf_kernel<<<64, 32>>>(x, y, T, start, end);
    reduce_kernel<<<1, 64>>>(out);
}

// round 4
// speedup vs baseline: 1.3404x; 1.3404x over previous
#include <cuda_runtime.h>
#include <cuda_bf16.h>
#include <cstdint>

// Problem constants
#define Bn 64
#define Sn 512
#define Dn 256
#define Hn 256
#define Ln 9

// ---------------------------------------------------------------------------
// Static device scratch
// ---------------------------------------------------------------------------
__device__ float g_Xperm[2u * 512u * 64u * 1024u];      // 268 MB
__device__ float g_Hbuf[2u * 512u * 64u * 256u];        // 67 MB
__device__ float g_hstate[2][2][Bn * Hn];               // [parity][dir]
__device__ float g_em[(size_t)Bn * Sn * Ln];
__device__ float g_res[Bn];
__device__ volatile unsigned g_barcnt[2];
__device__ volatile unsigned g_bargen[2];

__device__ __forceinline__ float fsig(float x) { return 1.0f / (1.0f + __expf(-x)); }
__device__ __forceinline__ float ftanh(float x) { return 2.0f / (1.0f + __expf(-2.0f * x)) - 1.0f; }

// ---------------------------------------------------------------------------
// Kernel 1: embedding gather + input projection GEMM (+bias), permuted write.
// ---------------------------------------------------------------------------
__global__ void embed_inproj_kernel(const int* __restrict__ x,
                                    const float* __restrict__ E,
                                    const float* __restrict__ Wih_f,
                                    const float* __restrict__ b_f,
                                    const float* __restrict__ Wih_b,
                                    const float* __restrict__ b_b) {
    const int dir = blockIdx.z;
    const float* __restrict__ W = dir ? Wih_b : Wih_f;
    const float* __restrict__ bias = dir ? b_b : b_f;
    const int s = blockIdx.y;
    const int n0 = blockIdx.x * 64;

    __shared__ float sA[16][68];
    __shared__ float sB[16][68];
    __shared__ int srow[64];

    const int tid = threadIdx.x;
    if (tid < 64) srow[tid] = x[tid * Sn + s];
    __syncthreads();

    const int tm = tid & 15;
    const int tn = tid >> 4;
    const int lrow = tid >> 2;
    const int kq = tid & 3;

    float acc[4][4];
#pragma unroll
    for (int c = 0; c < 4; c++)
#pragma unroll
        for (int d = 0; d < 4; d++) acc[c][d] = 0.0f;

    for (int k0 = 0; k0 < 256; k0 += 16) {
        float4 a4 = *reinterpret_cast<const float4*>(&E[(size_t)srow[lrow] * Dn + k0 + kq * 4]);
        float4 b4 = *reinterpret_cast<const float4*>(&W[(size_t)(n0 + lrow) * Dn + k0 + kq * 4]);
        __syncthreads();
        sA[kq * 4 + 0][lrow] = a4.x; sA[kq * 4 + 1][lrow] = a4.y;
        sA[kq * 4 + 2][lrow] = a4.z; sA[kq * 4 + 3][lrow] = a4.w;
        sB[kq * 4 + 0][lrow] = b4.x; sB[kq * 4 + 1][lrow] = b4.y;
        sB[kq * 4 + 2][lrow] = b4.z; sB[kq * 4 + 3][lrow] = b4.w;
        __syncthreads();
#pragma unroll
        for (int kk = 0; kk < 16; kk++) {
            float4 ra = *reinterpret_cast<float4*>(&sA[kk][4 * tm]);
            float4 rb = *reinterpret_cast<float4*>(&sB[kk][4 * tn]);
            acc[0][0] += ra.x * rb.x; acc[0][1] += ra.x * rb.y; acc[0][2] += ra.x * rb.z; acc[0][3] += ra.x * rb.w;
            acc[1][0] += ra.y * rb.x; acc[1][1] += ra.y * rb.y; acc[1][2] += ra.y * rb.z; acc[1][3] += ra.y * rb.w;
            acc[2][0] += ra.z * rb.x; acc[2][1] += ra.z * rb.y; acc[2][2] += ra.z * rb.z; acc[2][3] += ra.z * rb.w;
            acc[3][0] += ra.w * rb.x; acc[3][1] += ra.w * rb.y; acc[3][2] += ra.w * rb.z; acc[3][3] += ra.w * rb.w;
        }
    }

    const int n = n0 + 4 * tn;
    const int blk = (n & 255) >> 2;
    const int mg = n >> 8;
    const size_t tile_base = (((size_t)dir * Sn + s) * 64 + blk) * 1024;
    float bx = bias[n + 0], by = bias[n + 1], bz = bias[n + 2], bw = bias[n + 3];
#pragma unroll
    for (int c = 0; c < 4; c++) {
        const int b = 4 * tm + c;
        float4 v;
        v.x = acc[c][0] + bx; v.y = acc[c][1] + by;
        v.z = acc[c][2] + bz; v.w = acc[c][3] + bw;
        *reinterpret_cast<float4*>(&g_Xperm[tile_base + (size_t)b * 16 + mg * 4]) = v;
    }
}

// ---------------------------------------------------------------------------
// Grid barrier among the 64 blocks of one direction (sense-reversing).
// ---------------------------------------------------------------------------
__device__ __forceinline__ void dir_barrier(int dir) {
    __threadfence();
    __syncthreads();
    if (threadIdx.x == 0) {
        unsigned g = g_bargen[dir];
        unsigned prev = atomicAdd((unsigned*)&g_barcnt[dir], 1u);
        if (prev == 63u) {
            g_barcnt[dir] = 0u;
            __threadfence();
            g_bargen[dir] = g + 1u;
        } else {
            while (g_bargen[dir] == g) { }
        }
    }
    __syncthreads();
}

// ---------------------------------------------------------------------------
// Kernel 2: persistent bidirectional LSTM recurrence (pipelined).
// 128 blocks (64/dir), 256 threads. Block (dir,blk) owns gate rows
// {m*256 + blk*4 + r}. Warp mapping for the dot products:
//   warp w: jq = w&3 (handles j = 4*jq..4*jq+3, broadcast sW reads),
//           b  = (w>>2)*32 + lane (32 batches per warp half).
// h-chunk loads double-buffered in registers; X(s+1) prefetched under the
// grid barrier.
// ---------------------------------------------------------------------------
__global__ void lstm_recur_kernel(const float* __restrict__ Whh_f,
                                  const float* __restrict__ Whh_b) {
    const int dir = blockIdx.x >> 6;
    const int blk = blockIdx.x & 63;
    const float* __restrict__ Whh = dir ? Whh_b : Whh_f;

    __shared__ float sW[16][256];   // 16 KB stationary weights
    __shared__ float sh[64][68];    // 17.4 KB h chunk (pad: conflict-free LDS.128)
    __shared__ float sG[64][17];    // gates
    __shared__ float sC[64][4];     // cell state

    const int tid = threadIdx.x;

    for (int i = tid; i < 4096; i += 256) {
        int jl = i >> 8, k = i & 255;
        sW[jl][k] = Whh[(size_t)(((jl >> 2) << 8) + (blk << 2) + (jl & 3)) * Hn + k];
    }
    {
        int ub0 = tid >> 2, ur0 = tid & 3;
        sC[ub0][ur0] = 0.0f;
        g_hstate[0][dir][blk * 256 + tid] = 0.0f;
    }
    dir_barrier(dir);

    // compute mapping
    const int jq4 = ((tid >> 5) & 3) * 4;             // warp's 4 j-rows
    const int bh = ((tid >> 7) << 5) + (tid & 31);    // warp's batch row
    // update mapping
    const int ub = tid >> 2, ur = tid & 3;
    // loader mapping (4 float4 per thread per chunk)
    const int lb0 = tid >> 4;             const int lk0 = (tid & 15) * 4;
    const int lb1 = (tid + 256) >> 4;     const int lk1 = lk0;
    const int lb2 = (tid + 512) >> 4;     const int lk2 = lk0;
    const int lb3 = (tid + 768) >> 4;     const int lk3 = lk0;

    // prefetch X for step 0
    const int s_first = dir ? 511 : 0;
    float4 xv = *reinterpret_cast<const float4*>(
        &g_Xperm[(((size_t)dir * Sn + s_first) * 64 + blk) * 1024 + tid * 4]);

    for (int step = 0; step < 512; step++) {
        const int s = dir ? (511 - step) : step;
        const int par = step & 1;
        const float* __restrict__ hin = g_hstate[par][dir];
        float* __restrict__ hout = g_hstate[par ^ 1][dir];

        // deposit prefetched X tile into sG (gate accumulator base)
        {
            int bb = tid >> 2, jl = (tid & 3) * 4;
            sG[bb][jl + 0] = xv.x; sG[bb][jl + 1] = xv.y;
            sG[bb][jl + 2] = xv.z; sG[bb][jl + 3] = xv.w;
        }

        // issue h chunk-0 loads
        float4 r0 = __ldcg(reinterpret_cast<const float4*>(&hin[lb0 * 256 + 0 + lk0]));
        float4 r1 = __ldcg(reinterpret_cast<const float4*>(&hin[lb1 * 256 + 0 + lk1]));
        float4 r2 = __ldcg(reinterpret_cast<const float4*>(&hin[lb2 * 256 + 0 + lk2]));
        float4 r3 = __ldcg(reinterpret_cast<const float4*>(&hin[lb3 * 256 + 0 + lk3]));

        float a0 = 0.f, a1 = 0.f, a2 = 0.f, a3 = 0.f;
#pragma unroll
        for (int kc = 0; kc < 4; kc++) {
            // deposit regs into sh
            *reinterpret_cast<float4*>(&sh[lb0][lk0]) = r0;
            *reinterpret_cast<float4*>(&sh[lb1][lk1]) = r1;
            *reinterpret_cast<float4*>(&sh[lb2][lk2]) = r2;
            *reinterpret_cast<float4*>(&sh[lb3][lk3]) = r3;
            __syncthreads();
            const int kb = kc << 6;
            if (kc < 3) {
                const int kn = kb + 64;
                r0 = __ldcg(reinterpret_cast<const float4*>(&hin[lb0 * 256 + kn + lk0]));
                r1 = __ldcg(reinterpret_cast<const float4*>(&hin[lb1 * 256 + kn + lk1]));
                r2 = __ldcg(reinterpret_cast<const float4*>(&hin[lb2 * 256 + kn + lk2]));
                r3 = __ldcg(reinterpret_cast<const float4*>(&hin[lb3 * 256 + kn + lk3]));
            } else if (step < 511) {
                const int sn = dir ? (510 - step) : (step + 1);
                xv = *reinterpret_cast<const float4*>(
                    &g_Xperm[(((size_t)dir * Sn + sn) * 64 + blk) * 1024 + tid * 4]);
            }
#pragma unroll
            for (int kk = 0; kk < 16; kk++) {
                float4 h  = *reinterpret_cast<const float4*>(&sh[bh][kk * 4]);
                float4 w0 = *reinterpret_cast<const float4*>(&sW[jq4 + 0][kb + kk * 4]);
                float4 w1 = *reinterpret_cast<const float4*>(&sW[jq4 + 1][kb + kk * 4]);
                float4 w2 = *reinterpret_cast<const float4*>(&sW[jq4 + 2][kb + kk * 4]);
                float4 w3 = *reinterpret_cast<const float4*>(&sW[jq4 + 3][kb + kk * 4]);
                a0 += h.x * w0.x + h.y * w0.y + h.z * w0.z + h.w * w0.w;
                a1 += h.x * w1.x + h.y * w1.y + h.z * w1.z + h.w * w1.w;
                a2 += h.x * w2.x + h.y * w2.y + h.z * w2.z + h.w * w2.w;
                a3 += h.x * w3.x + h.y * w3.y + h.z * w3.z + h.w * w3.w;
            }
            __syncthreads();
        }
        // epilogue: accumulate into gates (distinct (b,j) per thread)
        sG[bh][jq4 + 0] += a0;
        sG[bh][jq4 + 1] += a1;
        sG[bh][jq4 + 2] += a2;
        sG[bh][jq4 + 3] += a3;
        __syncthreads();

        // pointwise LSTM cell update
        {
            float gi = sG[ub][0 + ur];
            float gf = sG[ub][4 + ur];
            float gg = sG[ub][8 + ur];
            float go = sG[ub][12 + ur];
            float c = sC[ub][ur];
            c = fsig(gf) * c + fsig(gi) * ftanh(gg);
            float h = fsig(go) * ftanh(c);
            sC[ub][ur] = c;
            const int hcol = (blk << 2) + ur;
            hout[ub * 256 + hcol] = h;
            g_Hbuf[(((size_t)dir * Sn + s) * Bn + ub) * Hn + hcol] = h;
        }
        dir_barrier(dir);
    }
}

// ---------------------------------------------------------------------------
// Kernel 3: emissions em[b][s][l] = [hf,hb] @ Wo + bo. One warp per (s,b).
// ---------------------------------------------------------------------------
__global__ void emissions_kernel(const float* __restrict__ Wo,
                                 const float* __restrict__ bo) {
    const int warp = (blockIdx.x * blockDim.x + threadIdx.x) >> 5;
    const int lane = threadIdx.x & 31;
    if (warp >= Bn * Sn) return;
    const int s = warp >> 6;
    const int b = warp & 63;
    const float* __restrict__ hf = &g_Hbuf[(((size_t)0 * Sn + s) * Bn + b) * Hn];
    const float* __restrict__ hb = &g_Hbuf[(((size_t)1 * Sn + s) * Bn + b) * Hn];

    float acc[9];
#pragma unroll
    for (int j = 0; j < 9; j++) acc[j] = 0.0f;

    for (int k = lane; k < 256; k += 32) {
        float vf = hf[k];
        float vb = hb[k];
        const float* w1 = &Wo[(size_t)k * Ln];
        const float* w2 = &Wo[(size_t)(256 + k) * Ln];
#pragma unroll
        for (int j = 0; j < 9; j++) acc[j] += vf * w1[j] + vb * w2[j];
    }
#pragma unroll
    for (int j = 0; j < 9; j++) {
        float v = acc[j];
#pragma unroll
        for (int o = 16; o; o >>= 1) v += __shfl_down_sync(0xffffffffu, v, o);
        if (lane == 0) g_em[((size_t)b * Sn + s) * Ln + j] = v + bo[j];
    }
}

// ---------------------------------------------------------------------------
// Kernel 4: CRF forward (logZ, register alpha + shfl broadcast) and
// gold score (t-parallel across lanes). One warp per batch.
// ---------------------------------------------------------------------------
__global__ void crf_kernel(const int* __restrict__ x,
                           const int* __restrict__ y,
                           const float* __restrict__ T,
                           const float* __restrict__ start,
                           const float* __restrict__ end) {
    const int b = blockIdx.x;
    const int lane = threadIdx.x;
    const float* __restrict__ em = &g_em[(size_t)b * Sn * Ln];
    const int* __restrict__ xb = &x[b * Sn];
    const int* __restrict__ yb = &y[b * Sn];
    const bool act = lane < 9;

    float Tcol[9];
    if (act) {
#pragma unroll
        for (int i = 0; i < 9; i++) Tcol[i] = T[i * 9 + lane];
    }
    float alpha = act ? (start[lane] + em[lane]) : -1e30f;

    for (int t = 1; t < Sn; t++) {
        int xt = __ldg(&xb[t]);
        float emt = act ? __ldg(&em[t * Ln + lane]) : 0.0f;
        float ai[9];
#pragma unroll
        for (int i = 0; i < 9; i++) ai[i] = __shfl_sync(0xffffffffu, alpha, i);
        if (xt != 0) {
            float v[9];
#pragma unroll
            for (int i = 0; i < 9; i++) v[i] = ai[i] + Tcol[i];
            float m01 = fmaxf(v[0], v[1]), m23 = fmaxf(v[2], v[3]);
            float m45 = fmaxf(v[4], v[5]), m67 = fmaxf(v[6], v[7]);
            float mx = fmaxf(fmaxf(fmaxf(m01, m23), fmaxf(m45, m67)), v[8]);
            float ssum = 0.0f;
#pragma unroll
            for (int i = 0; i < 9; i++) ssum += __expf(v[i] - mx);
            float na = mx + __logf(ssum) + emt;
            if (act) alpha = na;
        }
    }

    // logZ = logsumexp over 9 labels
    float vz = act ? (alpha + end[lane]) : -1e30f;
    float mx = vz;
#pragma unroll
    for (int o = 16; o; o >>= 1) mx = fmaxf(mx, __shfl_xor_sync(0xffffffffu, mx, o));
    float e = act ? __expf(vz - mx) : 0.0f;
#pragma unroll
    for (int o = 16; o; o >>= 1) e += __shfl_xor_sync(0xffffffffu, e, o);
    float logZ = mx + __logf(e);

    // gold score: t-parallel (prev label is y[t-1], no carried dependency)
    float gs = 0.0f;
    int cnt = 0;
    for (int t = lane; t < Sn; t += 32) {
        int m = (__ldg(&xb[t]) != 0) ? 1 : 0;
        cnt += m;
        if (t >= 1 && m) {
            int yt = __ldg(&yb[t]);
            int yp = __ldg(&yb[t - 1]);
            gs += T[yp * 9 + yt] + em[t * Ln + yt];
        }
    }
#pragma unroll
    for (int o = 16; o; o >>= 1) {
        gs  += __shfl_xor_sync(0xffffffffu, gs, o);
        cnt += __shfl_xor_sync(0xffffffffu, cnt, o);
    }

    if (lane == 0) {
        int y0 = yb[0];
        float score = start[y0] + em[y0] + gs;
        int last = cnt - 1;
        if (last < 0) last = 0;
        score += end[yb[last]];
        g_res[b] = logZ - score;
    }
}

// ---------------------------------------------------------------------------
// Kernel 5: mean over batch -> scalar output
// ---------------------------------------------------------------------------
__global__ void reduce_kernel(float* __restrict__ out) {
    __shared__ float s[64];
    s[threadIdx.x] = g_res[threadIdx.x];
    __syncthreads();
    if (threadIdx.x == 0) {
        float t = 0.0f;
        for (int i = 0; i < 64; i++) t += s[i];
        out[0] = t * (1.0f / 64.0f);
    }
}

// ---------------------------------------------------------------------------
extern "C" void kernel_launch(void* const* d_in, const int* in_sizes, int n_in,
                              void* d_out, int out_size) {
    const int*   x      = (const int*)  d_in[0];
    const int*   y      = (const int*)  d_in[1];
    const float* E      = (const float*)d_in[2];
    const float* Wih_f  = (const float*)d_in[3];
    const float* Whh_f  = (const float*)d_in[4];
    const float* b_f    = (const float*)d_in[5];
    const float* Wih_b  = (const float*)d_in[6];
    const float* Whh_b  = (const float*)d_in[7];
    const float* b_b    = (const float*)d_in[8];
    const float* Wo     = (const float*)d_in[9];
    const float* bo     = (const float*)d_in[10];
    const float* T      = (const float*)d_in[11];
    const float* start  = (const float*)d_in[12];
    const float* end    = (const float*)d_in[13];
    float* out = (float*)d_out;

    dim3 gemm_grid(16, 512, 2);
    embed_inproj_kernel<<<gemm_grid, 256>>>(x, E, Wih_f, b_f, Wih_b, b_b);
    lstm_recur_kernel<<<128, 256>>>(Whh_f, Whh_b);
    emissions_kernel<<<4096, 256>>>(Wo, bo);
    crf_kernel<<<64, 32>>>(x, y, T, start, end);
    reduce_kernel<<<1, 64>>>(out);
}